// round 11
// baseline (speedup 1.0000x reference)
#include <cuda_runtime.h>
#include <cuda_fp16.h>

#define NN 50000
#define D 128
#define EE 800000
#define CAP 128

typedef unsigned long long ull;

// Scratch (device globals: allocation-free; zero-initialized at module load,
// and kernels restore zero-state after last use so graph replays see
// identical initial conditions).
__device__ __align__(16) __half g_h[NN * D];    // fp16 features (both layers)
__device__ __align__(16) float g_x1[NN * D];    // layer-1 activations (f32)
__device__ float g_deg[NN];                     // edge-weight sums (excl. self loop)
__device__ float g_dinv[NN];
__device__ int   g_cur[NN];                     // per-dst fill count (= degree)
__device__ __align__(16) int2 g_bucket[(size_t)NN * CAP];  // (src, ew bits)
__device__ int   g_detect = 0;                  // 0 => int64 edges, 1 => int32 (sticky)

// ---- packed f32x2 helpers (sm_103a) ---------------------------------------
__device__ __forceinline__ ull pk2(float a) {
    ull r; asm("mov.b64 %0, {%1, %1};" : "=l"(r) : "f"(a)); return r;
}
__device__ __forceinline__ ull pkf2(float2 a) {
    ull r; asm("mov.b64 %0, {%1, %2};" : "=l"(r) : "f"(a.x), "f"(a.y)); return r;
}
__device__ __forceinline__ void fma2(ull& d, ull a, ull b) {
    asm("fma.rn.f32x2 %0, %1, %2, %0;" : "+l"(d) : "l"(a), "l"(b));
}
__device__ __forceinline__ float2 unpk(ull a) {
    float2 r; asm("mov.b64 {%0, %1}, %2;" : "=f"(r.x), "=f"(r.y) : "l"(a)); return r;
}

// fp16x4 (one ull) -> two packed f32x2 operands
__device__ __forceinline__ void h4_to_f2x2(ull h, ull& lo, ull& hi) {
    unsigned int ulo = (unsigned int)h;
    unsigned int uhi = (unsigned int)(h >> 32);
    float2 flo = __half22float2(*reinterpret_cast<__half2*>(&ulo));
    float2 fhi = __half22float2(*reinterpret_cast<__half2*>(&uhi));
    lo = pkf2(flo);
    hi = pkf2(fhi);
}

__device__ __forceinline__ int ld_edge(const void* ei, long long pos, int is32) {
    if (is32) return ((const int*)ei)[pos];
    return (int)((const long long*)ei)[pos];
}

// ---------------------------------------------------------------------------
// Prep 1: edge-dtype probe (sticky; idempotent across replays)
// ---------------------------------------------------------------------------
__global__ void detect_kernel(const int* __restrict__ ei32, int E) {
    int acc = 0;
    for (int k = threadIdx.x; k < 2048 && k < E; k += blockDim.x)
        acc |= ei32[2 * k + 1];
    if (acc) atomicOr(&g_detect, 1);
}

// Prep 2 (FUSED single edge pass): degree accumulate + bucket scatter.
// Bucket slots are fixed-stride, so no offsets/scan needed at all.
__global__ void hist_scatter_kernel(const void* __restrict__ ei,
                                    const float* __restrict__ ew, int E, int n) {
    int e = blockIdx.x * blockDim.x + threadIdx.x;
    if (e < E) {
        int is32 = g_detect;
        int s = ld_edge(ei, e, is32);
        int d = ld_edge(ei, (long long)E + e, is32);
        if ((unsigned)s >= (unsigned)n || (unsigned)d >= (unsigned)n) return;
        float w = ew[e];
        atomicAdd(&g_deg[d], w);
        int pos = atomicAdd(&g_cur[d], 1);
        if (pos < CAP)
            g_bucket[(size_t)d * CAP + pos] = make_int2(s, __float_as_int(w));
    }
}

// Prep 3: dinv (self-loop weight 1 folded in); resets g_deg for next replay.
__global__ void dinv_kernel(int n) {
    int i = blockIdx.x * blockDim.x + threadIdx.x;
    if (i < n) {
        g_dinv[i] = rsqrtf(g_deg[i] + 1.0f);
        g_deg[i] = 0.0f;   // restore zero-state
    }
}

// ---------------------------------------------------------------------------
// GEMM: g_h(fp16) = X(f32) * W. Block 128 threads, 16 nodes (measured-best).
// ---------------------------------------------------------------------------
__global__ void gemm_kernel(const float* __restrict__ X,
                            const float* __restrict__ W, int n) {
    __shared__ float xsT[D][20];  // [k][node], padded stride
    int node0 = blockIdx.x * 16;
    int t = threadIdx.x;

#pragma unroll
    for (int r = 0; r < 16; r++) {
        float v = (node0 + r < n) ? __ldg(X + (size_t)(node0 + r) * D + t) : 0.f;
        xsT[t][r] = v;
    }
    __syncthreads();

    int tx = t & 31;
    int tg = t >> 5;

    ull acc[4][2];
#pragma unroll
    for (int i = 0; i < 4; i++) { acc[i][0] = 0ull; acc[i][1] = 0ull; }

#pragma unroll 2
    for (int k = 0; k < D; k++) {
        longlong2 w2 = __ldg((const longlong2*)W + (size_t)k * 32 + tx);
        float4 xv = *(const float4*)&xsT[k][tg * 4];  // broadcast LDS.128
        ull wlo = (ull)w2.x, whi = (ull)w2.y;
        ull xp;
        xp = pk2(xv.x); fma2(acc[0][0], xp, wlo); fma2(acc[0][1], xp, whi);
        xp = pk2(xv.y); fma2(acc[1][0], xp, wlo); fma2(acc[1][1], xp, whi);
        xp = pk2(xv.z); fma2(acc[2][0], xp, wlo); fma2(acc[2][1], xp, whi);
        xp = pk2(xv.w); fma2(acc[3][0], xp, wlo); fma2(acc[3][1], xp, whi);
    }

#pragma unroll
    for (int i = 0; i < 4; i++) {
        int node = node0 + tg * 4 + i;
        if (node < n) {
            float2 p0 = unpk(acc[i][0]);
            float2 p1 = unpk(acc[i][1]);
            __half2 h0 = __floats2half2_rn(p0.x, p0.y);
            __half2 h1 = __floats2half2_rn(p1.x, p1.y);
            uint2 v;
            v.x = *reinterpret_cast<unsigned int*>(&h0);
            v.y = *reinterpret_cast<unsigned int*>(&h1);
            ((uint2*)(g_h + (size_t)node * D))[tx] = v;
        }
    }
}

// ---------------------------------------------------------------------------
// Pull aggregation: warp per dst node, lane owns 4 dims (fp16 gather, f32 acc)
// Norm coefficient computed on the fly: dinv[s] * ew * dinv[d].
// ---------------------------------------------------------------------------
__device__ __forceinline__ void agg_core(int node, int lane, ull& a0, ull& a1) {
    int cnt = min(g_cur[node], CAP);
    const int2* bk = g_bucket + (size_t)node * CAP;
    const ull* hv = (const ull*)g_h;   // 4 halves per lane slot
    float dv = g_dinv[node];

    int j = 0;
    for (; j + 1 < cnt; j += 2) {
        int2 r0 = __ldg(&bk[j]);
        int2 r1 = __ldg(&bk[j + 1]);
        float ds0 = __ldg(&g_dinv[r0.x]);
        float ds1 = __ldg(&g_dinv[r1.x]);
        ull h0 = __ldg(hv + (size_t)r0.x * 32 + lane);
        ull h1 = __ldg(hv + (size_t)r1.x * 32 + lane);
        float c0 = ds0 * __int_as_float(r0.y) * dv;
        float c1 = ds1 * __int_as_float(r1.y) * dv;
        ull l0, u0, l1, u1;
        h4_to_f2x2(h0, l0, u0);
        h4_to_f2x2(h1, l1, u1);
        ull cp0 = pk2(c0), cp1 = pk2(c1);
        fma2(a0, cp0, l0); fma2(a1, cp0, u0);
        fma2(a0, cp1, l1); fma2(a1, cp1, u1);
    }
    if (j < cnt) {
        int2 r0 = __ldg(&bk[j]);
        float ds0 = __ldg(&g_dinv[r0.x]);
        ull h0 = __ldg(hv + (size_t)r0.x * 32 + lane);
        float c0 = ds0 * __int_as_float(r0.y) * dv;
        ull l0, u0;
        h4_to_f2x2(h0, l0, u0);
        ull cp0 = pk2(c0);
        fma2(a0, cp0, l0); fma2(a1, cp0, u0);
    }

    // self-loop: + dinv^2 * h[node]
    ull slp = pk2(dv * dv);
    ull hs = hv[(size_t)node * 32 + lane];
    ull ls, us;
    h4_to_f2x2(hs, ls, us);
    fma2(a0, slp, ls); fma2(a1, slp, us);
}

__global__ void agg1_kernel(const float* __restrict__ b, int n) {
    int node = blockIdx.x * 8 + (threadIdx.x >> 5);
    int lane = threadIdx.x & 31;
    if (node >= n) return;

    ull a0 = 0ull, a1 = 0ull;
    agg_core(node, lane, a0, a1);

    float2 p0 = unpk(a0), p1 = unpk(a1);
    float4 bias = __ldg((const float4*)b + lane);
    float4 v;
    v.x = fmaxf(p0.x + bias.x, 0.f);
    v.y = fmaxf(p0.y + bias.y, 0.f);
    v.z = fmaxf(p1.x + bias.z, 0.f);
    v.w = fmaxf(p1.y + bias.w, 0.f);
    ((float4*)g_x1)[(size_t)node * 32 + lane] = v;
}

__global__ void agg2_kernel(const float* __restrict__ b,
                            float* __restrict__ out, int n) {
    int node = blockIdx.x * 8 + (threadIdx.x >> 5);
    int lane = threadIdx.x & 31;
    if (node >= n) return;

    ull a0 = 0ull, a1 = 0ull;
    agg_core(node, lane, a0, a1);

    if (lane == 0) g_cur[node] = 0;   // restore zero-state (last use)

    float2 p0 = unpk(a0), p1 = unpk(a1);
    float4 bias = __ldg((const float4*)b + lane);
    float4 v2;
    v2.x = fmaxf(p0.x + bias.x, 0.f);
    v2.y = fmaxf(p0.y + bias.y, 0.f);
    v2.z = fmaxf(p1.x + bias.z, 0.f);
    v2.w = fmaxf(p1.y + bias.w, 0.f);

    float4 v1 = ((const float4*)g_x1)[(size_t)node * 32 + lane];
    float4 lo = make_float4(v1.x, v2.x, v1.y, v2.y);
    float4 hi = make_float4(v1.z, v2.z, v1.w, v2.w);
    size_t o = (size_t)node * 64 + (size_t)lane * 2;
    ((float4*)out)[o] = lo;
    ((float4*)out)[o + 1] = hi;
}

// ---------------------------------------------------------------------------
extern "C" void kernel_launch(void* const* d_in, const int* in_sizes, int n_in,
                              void* d_out, int out_size) {
    const float* x = (const float*)d_in[0];
    const void* ei = d_in[1];
    const float* ew = (const float*)d_in[2];
    const float* W1 = (const float*)d_in[3];
    const float* b1 = (const float*)d_in[4];
    const float* W2 = (const float*)d_in[5];
    const float* b2 = (const float*)d_in[6];
    float* out = (float*)d_out;

    int n = in_sizes[0] / D;   // 50000
    int E = in_sizes[2];       // 800000

    static cudaStream_t s2 = nullptr;
    static cudaEvent_t evRoot = nullptr, evPrep = nullptr;
    static const float* x1_ptr = nullptr;
    if (!s2) {
        cudaStreamCreateWithFlags(&s2, cudaStreamNonBlocking);
        cudaEventCreateWithFlags(&evRoot, cudaEventDisableTiming);
        cudaEventCreateWithFlags(&evPrep, cudaEventDisableTiming);
        void* p = nullptr;
        cudaGetSymbolAddress(&p, g_x1);
        x1_ptr = (const float*)p;
    }

    int tb = 256;
    int nodeBlocks = (n + tb - 1) / tb;
    int edgeBlocks = (E + tb - 1) / tb;
    int gemmBlocks = (n + 15) / 16;
    int aggBlocks = (n + 7) / 8;

    // Fork point
    cudaEventRecord(evRoot, 0);

    // [1] GEMM1 on default stream
    gemm_kernel<<<gemmBlocks, 128>>>(x, W1, n);

    // Prep chain on s2 (concurrent with GEMM1): [2-4]
    cudaStreamWaitEvent(s2, evRoot, 0);
    detect_kernel<<<1, 256, 0, s2>>>((const int*)ei, E);
    hist_scatter_kernel<<<edgeBlocks, tb, 0, s2>>>(ei, ew, E, n);
    dinv_kernel<<<nodeBlocks, tb, 0, s2>>>(n);
    cudaEventRecord(evPrep, s2);

    // Join, then sequential main path: [5-7]
    cudaStreamWaitEvent(0, evPrep, 0);
    agg1_kernel<<<aggBlocks, tb>>>(b1, n);
    gemm_kernel<<<gemmBlocks, 128>>>(x1_ptr, W2, n);
    agg2_kernel<<<aggBlocks, tb>>>(b2, out, n);
}